// round 14
// baseline (speedup 1.0000x reference)
#include <cuda_runtime.h>
#include <cuda_fp16.h>
#include <math.h>
#include <stdint.h>

#define F_IN  512
#define F_HID 128
#define F_OUT 16
#define MAXN  100000
#define MAXE  1600000
#define SCAN_B 512
#define NSB   148          // scatter blocks inside the combined gemm kernel

// ---- scratch (static device globals; no allocation allowed) ----
// zeroed-per-call block: [deg (float) | cnt | fill | cursor]
__device__ __align__(16) int g_zblk[3 * MAXN + 4];
#define G_DEG  ((float*)g_zblk)
#define G_CNT  (g_zblk + MAXN)
#define G_FILL (g_zblk + 2 * MAXN)
#define G_CUR  (g_zblk + 3 * MAXN)

__device__ float g_dinv [MAXN];
__device__ int   g_off  [MAXN];
__device__ __align__(16) int2 g_edge[MAXE];       // CSR: (src, norm-as-int)
__device__ __align__(16) __half g_h1[(size_t)MAXN * F_HID];   // x @ W1 (fp16)
__device__ float g_z    [(size_t)MAXN * F_OUT];   // relu(agg)@W2
__device__ __align__(16) __half g_wt[F_HID * F_IN];   // W1^T fp16 [n][k]

// ======================= helpers ========================
__device__ __forceinline__ uint32_t smem_u32(const void* p) {
    uint32_t a;
    asm("{ .reg .u64 t; cvta.to.shared.u64 t, %1; cvt.u32.u64 %0, t; }"
        : "=r"(a) : "l"(p));
    return a;
}
#define SWZ64(o) ((o) ^ (((o) >> 3) & 0x30))

__device__ __forceinline__ void ldsm_x4(uint32_t* r, uint32_t addr) {
    asm volatile("ldmatrix.sync.aligned.m8n8.x4.shared.b16 {%0,%1,%2,%3}, [%4];"
                 : "=r"(r[0]), "=r"(r[1]), "=r"(r[2]), "=r"(r[3]) : "r"(addr));
}
__device__ __forceinline__ void mma_f16(float* d, const uint32_t* a, const uint32_t* b) {
    asm volatile(
        "mma.sync.aligned.m16n8k16.row.col.f32.f16.f16.f32 "
        "{%0,%1,%2,%3}, {%4,%5,%6,%7}, {%8,%9}, {%0,%1,%2,%3};"
        : "+f"(d[0]), "+f"(d[1]), "+f"(d[2]), "+f"(d[3])
        : "r"(a[0]), "r"(a[1]), "r"(a[2]), "r"(a[3]), "r"(b[0]), "r"(b[1]));
}
__device__ __forceinline__ void cp_async16(uint32_t dst, const void* src) {
    asm volatile("cp.async.ca.shared.global [%0], [%1], 16;" :: "r"(dst), "l"(src));
}
#define CP_COMMIT() asm volatile("cp.async.commit_group;" ::: "memory")
#define CP_WAIT0()  asm volatile("cp.async.wait_group 0;" ::: "memory")

// ======================= kernel 1: degree + count ============================
__global__ void deg_cnt_k(const int* __restrict__ dst, const float* __restrict__ ew, int E) {
    int e = blockIdx.x * blockDim.x + threadIdx.x;
    if (e < E) {
        int d = dst[e];
        atomicAdd(&G_DEG[d], ew[e]);
        atomicAdd(&G_CNT[d], 1);
    }
}

// ======================= kernel 2: scan+dinv  ||  wconv ======================
// blocks [0, nb): block-local exclusive scan + global cursor + dinv
// blocks [nb, nb+64): transpose + fp16-convert W1 into g_wt
__global__ __launch_bounds__(SCAN_B) void scanwconv_k(const float* __restrict__ W1,
                                                      int Nn, int nb) {
    if ((int)blockIdx.x >= nb) {
        int i = (blockIdx.x - nb) * SCAN_B + threadIdx.x;
        for (; i < F_HID * F_IN; i += 64 * SCAN_B) {
            int n = i >> 9;
            int k = i & 511;
            g_wt[i] = __float2half_rn(W1[(size_t)k * F_HID + n]);
        }
        return;
    }
    __shared__ int s[SCAN_B];
    __shared__ int sbase;
    int i = blockIdx.x * SCAN_B + threadIdx.x;
    int v = (i < Nn) ? G_CNT[i] : 0;
    s[threadIdx.x] = v;
    if (i < Nn) {
        float d = G_DEG[i] + 1.0f;   // self loop weight 1
        g_dinv[i] = d > 0.f ? rsqrtf(d) : 0.f;
    }
    __syncthreads();
#pragma unroll
    for (int o = 1; o < SCAN_B; o <<= 1) {
        int t = (threadIdx.x >= o) ? s[threadIdx.x - o] : 0;
        __syncthreads();
        s[threadIdx.x] += t;
        __syncthreads();
    }
    if (threadIdx.x == SCAN_B - 1)
        sbase = atomicAdd(G_CUR, s[SCAN_B - 1]);
    __syncthreads();
    if (i < Nn) g_off[i] = sbase + s[threadIdx.x] - v;
}

// ======================= kernel 3: scatter || GEMM1 ==========================
// blocks [0, NSB): grid-stride CSR scatter (L2/atomic-bound)
// blocks [NSB, ...): fp16 mma GEMM  g_h1 = (half)x @ (half)W1  (DRAM/tensor)
#define KC 32
#define STG 16384
#define PL_A 0
#define PL_B 8192
#define GEMM_SMEM (2 * STG)

__global__ __launch_bounds__(256, 2) void gemmscat_k(const float* __restrict__ x,
                                                     const int* __restrict__ src,
                                                     const int* __restrict__ dst,
                                                     const float* __restrict__ ew,
                                                     int Nn, int E) {
    if (blockIdx.x < NSB) {
        // ---- scatter portion ----
        int t = blockIdx.x * 256 + threadIdx.x;
        const int STRD = NSB * 256;
        for (int e = t; e < E; e += STRD) {
            int s = src[e];
            int d = dst[e];
            int pos = g_off[d] + atomicAdd(&G_FILL[d], 1);
            float norm = g_dinv[s] * ew[e] * g_dinv[d];
            g_edge[pos] = make_int2(s, __float_as_int(norm));
        }
        return;
    }

    // ---- GEMM portion ----
    extern __shared__ char smem[];
    uint32_t sb = smem_u32(smem);
    int tid  = threadIdx.x;
    int lane = tid & 31;
    int wid  = tid >> 5;
    int wm   = wid & 3;
    int wn   = wid >> 2;
    int row0 = (blockIdx.x - NSB) * 128;

#pragma unroll
    for (int i = 0; i < 2; i++) {
        int u = i * 256 + tid;
        int n = u >> 2;
        int c = u & 3;
        uint32_t off = SWZ64((uint32_t)(n * 64 + c * 16));
        cp_async16(sb + PL_B + off, g_wt + (size_t)n * F_IN + c * 8);
    }
    CP_COMMIT();

    float4 pA[4];
#pragma unroll
    for (int i = 0; i < 4; i++) {
        int u = i * 256 + tid;
        int r = u >> 3;
        int c4 = (u & 7) * 4;
        int gr = row0 + r;
        pA[i] = make_float4(0.f, 0.f, 0.f, 0.f);
        if (gr < Nn) pA[i] = *(const float4*)(x + (size_t)gr * F_IN + c4);
    }

    float acc[2][8][4];
#pragma unroll
    for (int a = 0; a < 2; a++)
#pragma unroll
        for (int b = 0; b < 8; b++)
#pragma unroll
            for (int c = 0; c < 4; c++) acc[a][b][c] = 0.f;

    for (int it = 0; it < F_IN / KC; it++) {
        int s = it & 1;
        char*    sm_s = smem + s * STG;
        uint32_t sb_s = sb + s * STG;

#pragma unroll
        for (int i = 0; i < 4; i++) {
            int u = i * 256 + tid;
            int r = u >> 3;
            int c4 = (u & 7) * 4;
            __half2 p0 = __floats2half2_rn(pA[i].x, pA[i].y);
            __half2 p1 = __floats2half2_rn(pA[i].z, pA[i].w);
            uint32_t off = SWZ64((uint32_t)(r * 64 + c4 * 2));
            *(uint2*)(sm_s + PL_A + off) =
                make_uint2(*(uint32_t*)&p0, *(uint32_t*)&p1);
        }
        CP_WAIT0();
        __syncthreads();

        if (it + 1 < F_IN / KC) {
            int kn = (it + 1) * KC;
            uint32_t sb_n = sb + (s ^ 1) * STG;
#pragma unroll
            for (int i = 0; i < 2; i++) {
                int u = i * 256 + tid;
                int n = u >> 2;
                int c = u & 3;
                uint32_t off = SWZ64((uint32_t)(n * 64 + c * 16));
                cp_async16(sb_n + PL_B + off, g_wt + (size_t)n * F_IN + kn + c * 8);
            }
            CP_COMMIT();
#pragma unroll
            for (int i = 0; i < 4; i++) {
                int u = i * 256 + tid;
                int r = u >> 3;
                int c4 = (u & 7) * 4;
                int gr = row0 + r;
                pA[i] = make_float4(0.f, 0.f, 0.f, 0.f);
                if (gr < Nn) pA[i] = *(const float4*)(x + (size_t)gr * F_IN + kn + c4);
            }
        }

#pragma unroll
        for (int ks = 0; ks < 2; ks++) {
            uint32_t a[2][4];
#pragma unroll
            for (int mt = 0; mt < 2; mt++) {
                uint32_t off = SWZ64((uint32_t)((wm * 32 + mt * 16 + (lane & 15)) * 64
                                                + ks * 32 + (lane >> 4) * 16));
                ldsm_x4(a[mt], sb_s + PL_A + off);
            }
#pragma unroll
            for (int ntp = 0; ntp < 4; ntp++) {
                uint32_t offB = SWZ64((uint32_t)((wn * 64 + ntp * 16 + (lane & 7)
                                                  + ((lane >> 4) & 1) * 8) * 64
                                                 + ks * 32 + ((lane >> 3) & 1) * 16));
                uint32_t b[4];
                ldsm_x4(b, sb_s + PL_B + offB);
#pragma unroll
                for (int sub = 0; sub < 2; sub++) {
#pragma unroll
                    for (int mt = 0; mt < 2; mt++)
                        mma_f16(acc[mt][ntp * 2 + sub], a[mt], b + sub * 2);
                }
            }
        }
    }

    int g4 = lane >> 2;
    int tg = lane & 3;
#pragma unroll
    for (int mt = 0; mt < 2; mt++) {
        int rbase = row0 + wm * 32 + mt * 16 + g4;
#pragma unroll
        for (int nt = 0; nt < 8; nt++) {
            int c = wn * 64 + nt * 8 + tg * 2;
            float* d = acc[mt][nt];
            if (rbase < Nn)
                *(__half2*)(g_h1 + (size_t)rbase * F_HID + c) = __floats2half2_rn(d[0], d[1]);
            if (rbase + 8 < Nn)
                *(__half2*)(g_h1 + (size_t)(rbase + 8) * F_HID + c) = __floats2half2_rn(d[2], d[3]);
        }
    }
}

// ======================= kernel 4: fused layer-1 =============================
// fp16 gather (predicated 8-blocks, MLP=8) + metadata prefetch + self loop +
// bias + relu + (h @ W2 via smem + butterfly) -> g_z   [byte-identical to R13]
__global__ __launch_bounds__(256, 4) void agg1_fused_k(const float* __restrict__ b1,
                                                       const float* __restrict__ W2,
                                                       int Nn) {
    __shared__ float4 sWv[F_OUT][32];
    int tid = threadIdx.x;
#pragma unroll
    for (int t = 0; t < 2; t++) {
        int idx = t * 256 + tid;
        int o  = idx >> 5;
        int ln = idx & 31;
        sWv[o][ln] = make_float4(W2[(size_t)(ln * 4 + 0) * F_OUT + o],
                                 W2[(size_t)(ln * 4 + 1) * F_OUT + o],
                                 W2[(size_t)(ln * 4 + 2) * F_OUT + o],
                                 W2[(size_t)(ln * 4 + 3) * F_OUT + o]);
    }
    __syncthreads();

    int lane  = tid & 31;
    int warp  = (blockIdx.x * blockDim.x + tid) >> 5;
    int nwarp = (gridDim.x * blockDim.x) >> 5;
    float4 bb = *(const float4*)(b1 + lane * 4);

    int node = warp;
    int base = 0, cnt = 0;
    if (node < Nn) { base = g_off[node]; cnt = G_CNT[node]; }

    while (node < Nn) {
        int nnode = node + nwarp;
        int nbase = 0, ncnt = 0;
        if (nnode < Nn) { nbase = __ldg(g_off + nnode); ncnt = __ldg(G_CNT + nnode); }

        float4 acc[4];
#pragma unroll
        for (int j = 0; j < 4; j++) acc[j] = make_float4(0.f, 0.f, 0.f, 0.f);

        for (int i = 0; i < cnt; i += 8) {
            int2  e[8];
            float nm[8];
#pragma unroll
            for (int j = 0; j < 8; j++) {
                int idx = i + j;
                bool ok = idx < cnt;
                e[j]  = __ldg(((const int2*)g_edge) + base + (ok ? idx : i));
                nm[j] = ok ? __int_as_float(e[j].y) : 0.f;
            }
            uint2 v[8];
#pragma unroll
            for (int j = 0; j < 8; j++) {
                v[j] = make_uint2(0u, 0u);
                if (i + j < cnt)
                    v[j] = __ldg(((const uint2*)(g_h1 + (size_t)e[j].x * F_HID)) + lane);
            }
#pragma unroll
            for (int j = 0; j < 8; j++) {
                float2 f0 = __half22float2(*(__half2*)&v[j].x);
                float2 f1 = __half22float2(*(__half2*)&v[j].y);
                float4& a = acc[j & 3];
                a.x = fmaf(f0.x, nm[j], a.x);
                a.y = fmaf(f0.y, nm[j], a.y);
                a.z = fmaf(f1.x, nm[j], a.z);
                a.w = fmaf(f1.y, nm[j], a.w);
            }
        }

        float dn  = g_dinv[node];
        float dn2 = dn * dn;
        uint2 sv = __ldg(((const uint2*)(g_h1 + (size_t)node * F_HID)) + lane);
        float2 s0 = __half22float2(*(__half2*)&sv.x);
        float2 s1 = __half22float2(*(__half2*)&sv.y);
        float4 h;
        h.x = fmaxf(acc[0].x + acc[1].x + acc[2].x + acc[3].x + s0.x * dn2 + bb.x, 0.f);
        h.y = fmaxf(acc[0].y + acc[1].y + acc[2].y + acc[3].y + s0.y * dn2 + bb.y, 0.f);
        h.z = fmaxf(acc[0].z + acc[1].z + acc[2].z + acc[3].z + s1.x * dn2 + bb.z, 0.f);
        h.w = fmaxf(acc[0].w + acc[1].w + acc[2].w + acc[3].w + s1.y * dn2 + bb.w, 0.f);

        float v16[16];
#pragma unroll
        for (int o = 0; o < 16; o++) {
            float4 w4 = sWv[o][lane];
            v16[o] = h.x * w4.x + h.y * w4.y + h.z * w4.z + h.w * w4.w;
        }

        {
            bool hi = (lane & 16) != 0;
#pragma unroll
            for (int j = 0; j < 8; j++) {
                float keep = hi ? v16[j + 8] : v16[j];
                float send = hi ? v16[j] : v16[j + 8];
                v16[j] = keep + __shfl_xor_sync(0xffffffffu, send, 16);
            }
        }
        {
            bool hi = (lane & 8) != 0;
#pragma unroll
            for (int j = 0; j < 4; j++) {
                float keep = hi ? v16[j + 4] : v16[j];
                float send = hi ? v16[j] : v16[j + 4];
                v16[j] = keep + __shfl_xor_sync(0xffffffffu, send, 8);
            }
        }
        {
            bool hi = (lane & 4) != 0;
#pragma unroll
            for (int j = 0; j < 2; j++) {
                float keep = hi ? v16[j + 2] : v16[j];
                float send = hi ? v16[j] : v16[j + 2];
                v16[j] = keep + __shfl_xor_sync(0xffffffffu, send, 4);
            }
        }
        {
            bool hi = (lane & 2) != 0;
            float keep = hi ? v16[1] : v16[0];
            float send = hi ? v16[0] : v16[1];
            v16[0] = keep + __shfl_xor_sync(0xffffffffu, send, 2);
        }
        v16[0] += __shfl_xor_sync(0xffffffffu, v16[0], 1);
        if (!(lane & 1))
            g_z[(size_t)node * F_OUT + (lane >> 1)] = v16[0];

        node = nnode;
        base = nbase;
        cnt  = ncnt;
    }
}

// ======================= kernel 5: fused layer-2 =============================
__global__ __launch_bounds__(256, 6) void agg2_fused_k(const float* __restrict__ b2,
                                                       float* __restrict__ out,
                                                       int Nn) {
    int lane16 = threadIdx.x & 15;
    int gid    = (blockIdx.x * blockDim.x + threadIdx.x) >> 4;
    int ngrp   = (gridDim.x * blockDim.x) >> 4;
    float bias = b2[lane16];

    int node = gid;
    int base = 0, cnt = 0;
    if (node < Nn) { base = g_off[node]; cnt = G_CNT[node]; }

    while (node < Nn) {
        int nnode = node + ngrp;
        int nbase = 0, ncnt = 0;
        if (nnode < Nn) { nbase = __ldg(g_off + nnode); ncnt = __ldg(G_CNT + nnode); }

        float acc[4] = {0.f, 0.f, 0.f, 0.f};
        for (int i = 0; i < cnt; i += 8) {
            int2  e[8];
            float nm[8];
#pragma unroll
            for (int j = 0; j < 8; j++) {
                int idx = i + j;
                bool ok = idx < cnt;
                e[j]  = __ldg(((const int2*)g_edge) + base + (ok ? idx : i));
                nm[j] = ok ? __int_as_float(e[j].y) : 0.f;
            }
            float zv[8];
#pragma unroll
            for (int j = 0; j < 8; j++) {
                zv[j] = 0.f;
                if (i + j < cnt)
                    zv[j] = __ldg(g_z + (size_t)e[j].x * F_OUT + lane16);
            }
#pragma unroll
            for (int j = 0; j < 8; j++)
                acc[j & 3] = fmaf(zv[j], nm[j], acc[j & 3]);
        }

        float dn  = g_dinv[node];
        float dn2 = dn * dn;
        float l = acc[0] + acc[1] + acc[2] + acc[3]
                + g_z[(size_t)node * F_OUT + lane16] * dn2 + bias;

        float m = l;
#pragma unroll
        for (int o = 8; o >= 1; o >>= 1)
            m = fmaxf(m, __shfl_xor_sync(0xffffffffu, m, o));
        float e = __expf(l - m);
        float sum = e;
#pragma unroll
        for (int o = 8; o >= 1; o >>= 1)
            sum += __shfl_xor_sync(0xffffffffu, sum, o);

        out[(size_t)node * F_OUT + lane16] = l - m - __logf(sum);

        node = nnode;
        base = nbase;
        cnt  = ncnt;
    }
}

// ---------------------------------------------------------------------------
extern "C" void kernel_launch(void* const* d_in, const int* in_sizes, int n_in,
                              void* d_out, int out_size) {
    const float* x  = (const float*)d_in[0];
    const int*   ei = (const int*)  d_in[1];
    const float* ew = (const float*)d_in[2];
    const float* W1 = (const float*)d_in[3];
    const float* b1 = (const float*)d_in[4];
    const float* W2 = (const float*)d_in[5];
    const float* b2 = (const float*)d_in[6];
    float* out = (float*)d_out;

    int Nn = in_sizes[0] / F_IN;
    int E  = in_sizes[1] / 2;
    const int* src = ei;
    const int* dst = ei + E;
    int nb = (Nn + SCAN_B - 1) / SCAN_B;

    static void* zptr = nullptr;
    static bool attr_set = false;
    if (!zptr) cudaGetSymbolAddress(&zptr, g_zblk);
    if (!attr_set) {
        cudaFuncSetAttribute(gemmscat_k, cudaFuncAttributeMaxDynamicSharedMemorySize,
                             GEMM_SMEM);
        attr_set = true;
    }

    // single stream; graph nodes: memset -> 5 kernels
    cudaMemsetAsync(zptr, 0, (size_t)(3 * MAXN + 4) * sizeof(int), 0);
    deg_cnt_k<<<(E + 255) / 256, 256>>>(dst, ew, E);                       // k1
    scanwconv_k<<<nb + 64, SCAN_B>>>(W1, Nn, nb);                          // k2
    gemmscat_k<<<NSB + (Nn + 127) / 128, 256, GEMM_SMEM>>>(x, src, dst,
                                                           ew, Nn, E);    // k3
    agg1_fused_k<<<148 * 4, 256>>>(b1, W2, Nn);                            // k4 <- target
    agg2_fused_k<<<148 * 6, 256>>>(b2, out, Nn);                           // k5
}

// round 15
// speedup vs baseline: 1.1354x; 1.1354x over previous
#include <cuda_runtime.h>
#include <cuda_fp16.h>
#include <math.h>
#include <stdint.h>

#define F_IN  512
#define F_HID 128
#define F_OUT 16
#define MAXN  100000
#define MAXE  1600000
#define MAXE2 (MAXE + 8 * MAXN)   // padded CSR capacity
#define SCAN_B 512
#define NSB   148

// ---- scratch (static device globals; no allocation allowed) ----
// zeroed-per-call block: [deg (float) | cnt | fill | cursor]
__device__ __align__(16) int g_zblk[3 * MAXN + 4];
#define G_DEG  ((float*)g_zblk)
#define G_CNT  (g_zblk + MAXN)
#define G_FILL (g_zblk + 2 * MAXN)
#define G_CUR  (g_zblk + 3 * MAXN)

__device__ float g_dinv [MAXN];
__device__ int   g_off  [MAXN];
__device__ __align__(16) int2 g_edge[MAXE2];      // CSR: (src, norm-as-int), padded
__device__ __align__(16) __half g_h1[(size_t)MAXN * F_HID];   // x @ W1 (fp16)
__device__ float g_z    [(size_t)MAXN * F_OUT];   // relu(agg)@W2
__device__ __align__(16) __half g_wt[F_HID * F_IN];   // W1^T fp16 [n][k]

// ======================= helpers ========================
__device__ __forceinline__ uint32_t smem_u32(const void* p) {
    uint32_t a;
    asm("{ .reg .u64 t; cvta.to.shared.u64 t, %1; cvt.u32.u64 %0, t; }"
        : "=r"(a) : "l"(p));
    return a;
}
#define SWZ64(o) ((o) ^ (((o) >> 3) & 0x30))

__device__ __forceinline__ void ldsm_x4(uint32_t* r, uint32_t addr) {
    asm volatile("ldmatrix.sync.aligned.m8n8.x4.shared.b16 {%0,%1,%2,%3}, [%4];"
                 : "=r"(r[0]), "=r"(r[1]), "=r"(r[2]), "=r"(r[3]) : "r"(addr));
}
__device__ __forceinline__ void mma_f16(float* d, const uint32_t* a, const uint32_t* b) {
    asm volatile(
        "mma.sync.aligned.m16n8k16.row.col.f32.f16.f16.f32 "
        "{%0,%1,%2,%3}, {%4,%5,%6,%7}, {%8,%9}, {%0,%1,%2,%3};"
        : "+f"(d[0]), "+f"(d[1]), "+f"(d[2]), "+f"(d[3])
        : "r"(a[0]), "r"(a[1]), "r"(a[2]), "r"(a[3]), "r"(b[0]), "r"(b[1]));
}
__device__ __forceinline__ void cp_async16(uint32_t dst, const void* src) {
    asm volatile("cp.async.ca.shared.global [%0], [%1], 16;" :: "r"(dst), "l"(src));
}
#define CP_COMMIT() asm volatile("cp.async.commit_group;" ::: "memory")
#define CP_WAIT0()  asm volatile("cp.async.wait_group 0;" ::: "memory")

// ======================= kernel 1: degree + count ============================
__global__ void deg_cnt_k(const int* __restrict__ dst, const float* __restrict__ ew, int E) {
    int e = blockIdx.x * blockDim.x + threadIdx.x;
    if (e < E) {
        int d = dst[e];
        atomicAdd(&G_DEG[d], ew[e]);
        atomicAdd(&G_CNT[d], 1);
    }
}

// ======================= kernel 2: scan+dinv+pad  ||  wconv ==================
// blocks [0, nb): exclusive scan of PADDED counts + cursor + dinv + zero-fill
//                 of the padding slots in g_edge; G_CNT rewritten to padded cnt
// blocks [nb, nb+64): transpose + fp16-convert W1 into g_wt
__global__ __launch_bounds__(SCAN_B) void scanwconv_k(const float* __restrict__ W1,
                                                      int Nn, int nb) {
    if ((int)blockIdx.x >= nb) {
        int i = (blockIdx.x - nb) * SCAN_B + threadIdx.x;
        for (; i < F_HID * F_IN; i += 64 * SCAN_B) {
            int n = i >> 9;
            int k = i & 511;
            g_wt[i] = __float2half_rn(W1[(size_t)k * F_HID + n]);
        }
        return;
    }
    __shared__ int s[SCAN_B];
    __shared__ int sbase;
    int i = blockIdx.x * SCAN_B + threadIdx.x;
    int c  = (i < Nn) ? G_CNT[i] : 0;
    int cp = (c + 7) & ~7;                  // pad group to multiple of 8
    s[threadIdx.x] = cp;
    if (i < Nn) {
        float d = G_DEG[i] + 1.0f;          // self loop weight 1
        g_dinv[i] = d > 0.f ? rsqrtf(d) : 0.f;
    }
    __syncthreads();
#pragma unroll
    for (int o = 1; o < SCAN_B; o <<= 1) {
        int t = (threadIdx.x >= o) ? s[threadIdx.x - o] : 0;
        __syncthreads();
        s[threadIdx.x] += t;
        __syncthreads();
    }
    if (threadIdx.x == SCAN_B - 1)
        sbase = atomicAdd(G_CUR, s[SCAN_B - 1]);
    __syncthreads();
    if (i < Nn) {
        int base = sbase + s[threadIdx.x] - cp;
        g_off[i] = base;
        G_CNT[i] = cp;                       // agg kernels loop over padded cnt
        for (int k = c; k < cp; k++)         // zero-fill padding: src 0, norm 0
            g_edge[base + k] = make_int2(0, 0);
    }
}

// ======================= kernel 3: scatter || GEMM1 ==========================
#define KC 32
#define STG 16384
#define PL_A 0
#define PL_B 8192
#define GEMM_SMEM (2 * STG)

__global__ __launch_bounds__(256, 2) void gemmscat_k(const float* __restrict__ x,
                                                     const int* __restrict__ src,
                                                     const int* __restrict__ dst,
                                                     const float* __restrict__ ew,
                                                     int Nn, int E) {
    if (blockIdx.x < NSB) {
        int t = blockIdx.x * 256 + threadIdx.x;
        const int STRD = NSB * 256;
        for (int e = t; e < E; e += STRD) {
            int s = src[e];
            int d = dst[e];
            int pos = g_off[d] + atomicAdd(&G_FILL[d], 1);
            float norm = g_dinv[s] * ew[e] * g_dinv[d];
            g_edge[pos] = make_int2(s, __float_as_int(norm));
        }
        return;
    }

    extern __shared__ char smem[];
    uint32_t sb = smem_u32(smem);
    int tid  = threadIdx.x;
    int lane = tid & 31;
    int wid  = tid >> 5;
    int wm   = wid & 3;
    int wn   = wid >> 2;
    int row0 = (blockIdx.x - NSB) * 128;

#pragma unroll
    for (int i = 0; i < 2; i++) {
        int u = i * 256 + tid;
        int n = u >> 2;
        int c = u & 3;
        uint32_t off = SWZ64((uint32_t)(n * 64 + c * 16));
        cp_async16(sb + PL_B + off, g_wt + (size_t)n * F_IN + c * 8);
    }
    CP_COMMIT();

    float4 pA[4];
#pragma unroll
    for (int i = 0; i < 4; i++) {
        int u = i * 256 + tid;
        int r = u >> 3;
        int c4 = (u & 7) * 4;
        int gr = row0 + r;
        pA[i] = make_float4(0.f, 0.f, 0.f, 0.f);
        if (gr < Nn) pA[i] = *(const float4*)(x + (size_t)gr * F_IN + c4);
    }

    float acc[2][8][4];
#pragma unroll
    for (int a = 0; a < 2; a++)
#pragma unroll
        for (int b = 0; b < 8; b++)
#pragma unroll
            for (int c = 0; c < 4; c++) acc[a][b][c] = 0.f;

    for (int it = 0; it < F_IN / KC; it++) {
        int s = it & 1;
        char*    sm_s = smem + s * STG;
        uint32_t sb_s = sb + s * STG;

#pragma unroll
        for (int i = 0; i < 4; i++) {
            int u = i * 256 + tid;
            int r = u >> 3;
            int c4 = (u & 7) * 4;
            __half2 p0 = __floats2half2_rn(pA[i].x, pA[i].y);
            __half2 p1 = __floats2half2_rn(pA[i].z, pA[i].w);
            uint32_t off = SWZ64((uint32_t)(r * 64 + c4 * 2));
            *(uint2*)(sm_s + PL_A + off) =
                make_uint2(*(uint32_t*)&p0, *(uint32_t*)&p1);
        }
        CP_WAIT0();
        __syncthreads();

        if (it + 1 < F_IN / KC) {
            int kn = (it + 1) * KC;
            uint32_t sb_n = sb + (s ^ 1) * STG;
#pragma unroll
            for (int i = 0; i < 2; i++) {
                int u = i * 256 + tid;
                int n = u >> 2;
                int c = u & 3;
                uint32_t off = SWZ64((uint32_t)(n * 64 + c * 16));
                cp_async16(sb_n + PL_B + off, g_wt + (size_t)n * F_IN + kn + c * 8);
            }
            CP_COMMIT();
#pragma unroll
            for (int i = 0; i < 4; i++) {
                int u = i * 256 + tid;
                int r = u >> 3;
                int c4 = (u & 7) * 4;
                int gr = row0 + r;
                pA[i] = make_float4(0.f, 0.f, 0.f, 0.f);
                if (gr < Nn) pA[i] = *(const float4*)(x + (size_t)gr * F_IN + kn + c4);
            }
        }

#pragma unroll
        for (int ks = 0; ks < 2; ks++) {
            uint32_t a[2][4];
#pragma unroll
            for (int mt = 0; mt < 2; mt++) {
                uint32_t off = SWZ64((uint32_t)((wm * 32 + mt * 16 + (lane & 15)) * 64
                                                + ks * 32 + (lane >> 4) * 16));
                ldsm_x4(a[mt], sb_s + PL_A + off);
            }
#pragma unroll
            for (int ntp = 0; ntp < 4; ntp++) {
                uint32_t offB = SWZ64((uint32_t)((wn * 64 + ntp * 16 + (lane & 7)
                                                  + ((lane >> 4) & 1) * 8) * 64
                                                 + ks * 32 + ((lane >> 3) & 1) * 16));
                uint32_t b[4];
                ldsm_x4(b, sb_s + PL_B + offB);
#pragma unroll
                for (int sub = 0; sub < 2; sub++) {
#pragma unroll
                    for (int mt = 0; mt < 2; mt++)
                        mma_f16(acc[mt][ntp * 2 + sub], a[mt], b + sub * 2);
                }
            }
        }
    }

    int g4 = lane >> 2;
    int tg = lane & 3;
#pragma unroll
    for (int mt = 0; mt < 2; mt++) {
        int rbase = row0 + wm * 32 + mt * 16 + g4;
#pragma unroll
        for (int nt = 0; nt < 8; nt++) {
            int c = wn * 64 + nt * 8 + tg * 2;
            float* d = acc[mt][nt];
            if (rbase < Nn)
                *(__half2*)(g_h1 + (size_t)rbase * F_HID + c) = __floats2half2_rn(d[0], d[1]);
            if (rbase + 8 < Nn)
                *(__half2*)(g_h1 + (size_t)(rbase + 8) * F_HID + c) = __floats2half2_rn(d[2], d[3]);
        }
    }
}

// ======================= kernel 4: fused layer-1 =============================
// 2 edges per warp (lanes 0-15 even edge, 16-31 odd), uint4 row loads, padded
// groups (no predication) + self loop + bias + relu + h@W2 -> g_z
__global__ __launch_bounds__(256, 4) void agg1_fused_k(const float* __restrict__ b1,
                                                       const float* __restrict__ W2,
                                                       int Nn) {
    __shared__ float4 sWv[F_OUT][32];
    int tid = threadIdx.x;
#pragma unroll
    for (int t = 0; t < 2; t++) {
        int idx = t * 256 + tid;
        int o  = idx >> 5;
        int ln = idx & 31;
        sWv[o][ln] = make_float4(W2[(size_t)(ln * 4 + 0) * F_OUT + o],
                                 W2[(size_t)(ln * 4 + 1) * F_OUT + o],
                                 W2[(size_t)(ln * 4 + 2) * F_OUT + o],
                                 W2[(size_t)(ln * 4 + 3) * F_OUT + o]);
    }
    __syncthreads();

    int lane  = tid & 31;
    int l16   = lane & 15;
    int half  = lane >> 4;          // 0: even edge, 1: odd edge
    int warp  = (blockIdx.x * blockDim.x + tid) >> 5;
    int nwarp = (gridDim.x * blockDim.x) >> 5;
    float4 bb = *(const float4*)(b1 + lane * 4);

    int node = warp;
    int base = 0, cnt = 0;
    if (node < Nn) { base = g_off[node]; cnt = G_CNT[node]; }   // cnt padded to %8

    while (node < Nn) {
        int nnode = node + nwarp;
        int nbase = 0, ncnt = 0;
        if (nnode < Nn) { nbase = __ldg(g_off + nnode); ncnt = __ldg(G_CNT + nnode); }

        float a[8];
#pragma unroll
        for (int j = 0; j < 8; j++) a[j] = 0.f;

        for (int i = 0; i < cnt; i += 8) {
            // 4 pairs: this lane's edge index = i + 2t + half
            int2 e[4];
#pragma unroll
            for (int t = 0; t < 4; t++)
                e[t] = __ldg(((const int2*)g_edge) + base + i + 2 * t + half);
            uint4 v[4];
#pragma unroll
            for (int t = 0; t < 4; t++)
                v[t] = __ldg(((const uint4*)(g_h1 + (size_t)e[t].x * F_HID)) + l16);
#pragma unroll
            for (int t = 0; t < 4; t++) {
                float nm = __int_as_float(e[t].y);
                float2 f0 = __half22float2(*(__half2*)&v[t].x);
                float2 f1 = __half22float2(*(__half2*)&v[t].y);
                float2 f2 = __half22float2(*(__half2*)&v[t].z);
                float2 f3 = __half22float2(*(__half2*)&v[t].w);
                a[0] = fmaf(f0.x, nm, a[0]);
                a[1] = fmaf(f0.y, nm, a[1]);
                a[2] = fmaf(f1.x, nm, a[2]);
                a[3] = fmaf(f1.y, nm, a[3]);
                a[4] = fmaf(f2.x, nm, a[4]);
                a[5] = fmaf(f2.y, nm, a[5]);
                a[6] = fmaf(f3.x, nm, a[6]);
                a[7] = fmaf(f3.y, nm, a[7]);
            }
        }

        // merge even/odd halves: lane l and lane l+16 cover the same 8 cols
#pragma unroll
        for (int j = 0; j < 8; j++)
            a[j] += __shfl_xor_sync(0xffffffffu, a[j], 16);

        // redistribute to 32-lane x 4-col layout: lane m <- cols m*4..m*4+3
        int srcl = lane >> 1;
        float h4[4];
#pragma unroll
        for (int k = 0; k < 4; k++) {
            float lo = __shfl_sync(0xffffffffu, a[k],     srcl);
            float hi = __shfl_sync(0xffffffffu, a[4 + k], srcl);
            h4[k] = (lane & 1) ? hi : lo;
        }

        float dn  = g_dinv[node];
        float dn2 = dn * dn;
        uint2 sv = __ldg(((const uint2*)(g_h1 + (size_t)node * F_HID)) + lane);
        float2 s0 = __half22float2(*(__half2*)&sv.x);
        float2 s1 = __half22float2(*(__half2*)&sv.y);
        float4 h;
        h.x = fmaxf(h4[0] + s0.x * dn2 + bb.x, 0.f);
        h.y = fmaxf(h4[1] + s0.y * dn2 + bb.y, 0.f);
        h.z = fmaxf(h4[2] + s1.x * dn2 + bb.z, 0.f);
        h.w = fmaxf(h4[3] + s1.y * dn2 + bb.w, 0.f);

        float v16[16];
#pragma unroll
        for (int o = 0; o < 16; o++) {
            float4 w4 = sWv[o][lane];
            v16[o] = h.x * w4.x + h.y * w4.y + h.z * w4.z + h.w * w4.w;
        }

        // butterfly split reduction: 16 shuffles total
        {
            bool hi = (lane & 16) != 0;
#pragma unroll
            for (int j = 0; j < 8; j++) {
                float keep = hi ? v16[j + 8] : v16[j];
                float send = hi ? v16[j] : v16[j + 8];
                v16[j] = keep + __shfl_xor_sync(0xffffffffu, send, 16);
            }
        }
        {
            bool hi = (lane & 8) != 0;
#pragma unroll
            for (int j = 0; j < 4; j++) {
                float keep = hi ? v16[j + 4] : v16[j];
                float send = hi ? v16[j] : v16[j + 4];
                v16[j] = keep + __shfl_xor_sync(0xffffffffu, send, 8);
            }
        }
        {
            bool hi = (lane & 4) != 0;
#pragma unroll
            for (int j = 0; j < 2; j++) {
                float keep = hi ? v16[j + 2] : v16[j];
                float send = hi ? v16[j] : v16[j + 2];
                v16[j] = keep + __shfl_xor_sync(0xffffffffu, send, 4);
            }
        }
        {
            bool hi = (lane & 2) != 0;
            float keep = hi ? v16[1] : v16[0];
            float send = hi ? v16[0] : v16[1];
            v16[0] = keep + __shfl_xor_sync(0xffffffffu, send, 2);
        }
        v16[0] += __shfl_xor_sync(0xffffffffu, v16[0], 1);
        if (!(lane & 1))
            g_z[(size_t)node * F_OUT + (lane >> 1)] = v16[0];

        node = nnode;
        base = nbase;
        cnt  = ncnt;
    }
}

// ======================= kernel 5: fused layer-2 =============================
// padded groups (no predication), 16 lanes per node
__global__ __launch_bounds__(256, 6) void agg2_fused_k(const float* __restrict__ b2,
                                                       float* __restrict__ out,
                                                       int Nn) {
    int lane16 = threadIdx.x & 15;
    int gid    = (blockIdx.x * blockDim.x + threadIdx.x) >> 4;
    int ngrp   = (gridDim.x * blockDim.x) >> 4;
    float bias = b2[lane16];

    int node = gid;
    int base = 0, cnt = 0;
    if (node < Nn) { base = g_off[node]; cnt = G_CNT[node]; }

    while (node < Nn) {
        int nnode = node + ngrp;
        int nbase = 0, ncnt = 0;
        if (nnode < Nn) { nbase = __ldg(g_off + nnode); ncnt = __ldg(G_CNT + nnode); }

        float acc[4] = {0.f, 0.f, 0.f, 0.f};
        for (int i = 0; i < cnt; i += 8) {
            int2 e[8];
#pragma unroll
            for (int j = 0; j < 8; j++)
                e[j] = __ldg(((const int2*)g_edge) + base + i + j);
            float zv[8];
#pragma unroll
            for (int j = 0; j < 8; j++)
                zv[j] = __ldg(g_z + (size_t)e[j].x * F_OUT + lane16);
#pragma unroll
            for (int j = 0; j < 8; j++)
                acc[j & 3] = fmaf(zv[j], __int_as_float(e[j].y), acc[j & 3]);
        }

        float dn  = g_dinv[node];
        float dn2 = dn * dn;
        float l = acc[0] + acc[1] + acc[2] + acc[3]
                + g_z[(size_t)node * F_OUT + lane16] * dn2 + bias;

        float m = l;
#pragma unroll
        for (int o = 8; o >= 1; o >>= 1)
            m = fmaxf(m, __shfl_xor_sync(0xffffffffu, m, o));
        float e = __expf(l - m);
        float sum = e;
#pragma unroll
        for (int o = 8; o >= 1; o >>= 1)
            sum += __shfl_xor_sync(0xffffffffu, sum, o);

        out[(size_t)node * F_OUT + lane16] = l - m - __logf(sum);

        node = nnode;
        base = nbase;
        cnt  = ncnt;
    }
}

// ---------------------------------------------------------------------------
extern "C" void kernel_launch(void* const* d_in, const int* in_sizes, int n_in,
                              void* d_out, int out_size) {
    const float* x  = (const float*)d_in[0];
    const int*   ei = (const int*)  d_in[1];
    const float* ew = (const float*)d_in[2];
    const float* W1 = (const float*)d_in[3];
    const float* b1 = (const float*)d_in[4];
    const float* W2 = (const float*)d_in[5];
    const float* b2 = (const float*)d_in[6];
    float* out = (float*)d_out;

    int Nn = in_sizes[0] / F_IN;
    int E  = in_sizes[1] / 2;
    const int* src = ei;
    const int* dst = ei + E;
    int nb = (Nn + SCAN_B - 1) / SCAN_B;

    static void* zptr = nullptr;
    static bool attr_set = false;
    if (!zptr) cudaGetSymbolAddress(&zptr, g_zblk);
    if (!attr_set) {
        cudaFuncSetAttribute(gemmscat_k, cudaFuncAttributeMaxDynamicSharedMemorySize,
                             GEMM_SMEM);
        attr_set = true;
    }

    cudaMemsetAsync(zptr, 0, (size_t)(3 * MAXN + 4) * sizeof(int), 0);
    deg_cnt_k<<<(E + 255) / 256, 256>>>(dst, ew, E);                       // k1
    scanwconv_k<<<nb + 64, SCAN_B>>>(W1, Nn, nb);                          // k2
    gemmscat_k<<<NSB + (Nn + 127) / 128, 256, GEMM_SMEM>>>(x, src, dst,
                                                           ew, Nn, E);    // k3
    agg1_fused_k<<<148 * 4, 256>>>(b1, W2, Nn);                            // k4 <- profiled
    agg2_fused_k<<<148 * 6, 256>>>(b2, out, Nn);                           // k5
}